// round 4
// baseline (speedup 1.0000x reference)
#include <cuda_runtime.h>
#include <cstdint>

// Problem-size upper bounds (fixed by the dataset).
#define NMAX 100000
#define EMAX 1600000

// ---------------------------------------------------------------------------
// Static device scratch (allocation-free per harness rules).
// ---------------------------------------------------------------------------
__device__ float g_t1 [NMAX * 128];  // layer1 msgs t1 = x@W_l1^T ; reused as layer2 u (ld 64)
__device__ float g_pre[NMAX * 128];  // layer1 pre = x@W_r1^T ; becomes h in-place
__device__ float g_agg1[NMAX * 128]; // layer1 aggregation
__device__ float g_agg2[NMAX * 64];  // layer2 aggregation
__device__ float g_deg [NMAX];       // in-degree (float)
__device__ int   g_src [EMAX];       // decoded edge sources
__device__ int   g_dst [EMAX];       // decoded edge destinations
__device__ int   g_is64;             // 1 if edge_index is int64, 0 if int32

// ---------------------------------------------------------------------------
// Vectorized global reduction-add (no return), sm_90+.
// ---------------------------------------------------------------------------
__device__ __forceinline__ void red_add_v4(float* p, float4 v) {
#if defined(__CUDA_ARCH__) && (__CUDA_ARCH__ >= 900)
    asm volatile("red.global.add.v4.f32 [%0], {%1,%2,%3,%4};"
                 :: "l"(p), "f"(v.x), "f"(v.y), "f"(v.z), "f"(v.w) : "memory");
#else
    atomicAdd(p + 0, v.x);
    atomicAdd(p + 1, v.y);
    atomicAdd(p + 2, v.z);
    atomicAdd(p + 3, v.w);
#endif
}

// ---------------------------------------------------------------------------
// Detect edge_index dtype. int64 little-endian with values < 2^31 has zero
// high words at all odd int32 positions; random int32 indices do not.
// ---------------------------------------------------------------------------
__global__ void detect_kernel(const int* __restrict__ ei32) {
    if (threadIdx.x == 0 && blockIdx.x == 0) {
        int nz = 0;
        #pragma unroll
        for (int i = 1; i < 128; i += 2) nz |= ei32[i];
        g_is64 = (nz == 0) ? 1 : 0;
    }
}

// ---------------------------------------------------------------------------
// Decode indices to int32 arrays + count degrees.
// edge_index layout: [2, E] row-major → src at [0..E), dst at [E..2E).
// ---------------------------------------------------------------------------
__global__ void decode_deg_kernel(const void* __restrict__ ei, int E) {
    int e = blockIdx.x * blockDim.x + threadIdx.x;
    if (e >= E) return;
    int src, dst;
    if (g_is64) {
        const long long* p = (const long long*)ei;
        src = (int)p[e];
        dst = (int)p[E + e];
    } else {
        const int* p = (const int*)ei;
        src = p[e];
        dst = p[E + e];
    }
    g_src[e] = src;
    g_dst[e] = dst;
    atomicAdd(&g_deg[dst], 1.0f);
}

// ---------------------------------------------------------------------------
// Zero scratch: agg1 (N*128) + agg2 (N*64) + deg (N)
// ---------------------------------------------------------------------------
__global__ void zero_scratch(int N) {
    int i = blockIdx.x * blockDim.x + threadIdx.x;
    int n128 = N * 128;
    int n192 = N * 192;
    int tot  = N * 193;
    if (i >= tot) return;
    if (i < n128)       g_agg1[i] = 0.0f;
    else if (i < n192)  g_agg2[i - n128] = 0.0f;
    else                g_deg [i - n192] = 0.0f;
}

// ---------------------------------------------------------------------------
// Dual-output GEMM:  C = A[N,128] @ Wcat^T, Wcat = [W0 (n0 rows); W1], K=128.
// LAYER==1: A = x (ext),  n0=128, out0 = g_t1 (ld128), out1 = g_pre (ld128)
// LAYER==2: A = g_pre,    n0=64,  out0 = g_t1 (ld64),  out1 = d_out (ld64)
// BM=BN=128, BK=8, 256 threads, 8x8 register tile per thread.
// ---------------------------------------------------------------------------
template <int LAYER>
__global__ __launch_bounds__(256) void gemm_dual(
    const float* __restrict__ Aext,
    const float* __restrict__ W0,
    const float* __restrict__ W1,
    float* __restrict__ outExt,
    int N)
{
    constexpr int n0 = (LAYER == 1) ? 128 : 64;
    constexpr int LD = (LAYER == 1) ? 128 : 64;
    const float* A    = (LAYER == 1) ? Aext : g_pre;
    float*       out0 = g_t1;
    float*       out1 = (LAYER == 1) ? g_pre : outExt;

    constexpr int BK  = 8;
    constexpr int SLD = 132;              // padded smem stride
    __shared__ float sA[BK * SLD];
    __shared__ float sB[BK * SLD];

    const int tid     = threadIdx.x;
    const int rowBase = blockIdx.x * 128;
    const int jBase   = blockIdx.y * 128;

    const int lr  = tid >> 1;             // 0..127 : tile row (A) / tile col (W)
    const int lk4 = (tid & 1) * 4;        // k sub-offset 0 or 4

    const float* wrow;
    {
        int jg = jBase + lr;
        wrow = (jg < n0) ? (W0 + (size_t)jg * 128) : (W1 + (size_t)(jg - n0) * 128);
    }
    const bool   avalid = (rowBase + lr) < N;
    const float* arow   = A + (size_t)(rowBase + lr) * 128;

    const int row0 = (tid >> 4) * 8;
    const int col0 = (tid & 15) * 8;

    float acc[8][8];
    #pragma unroll
    for (int i = 0; i < 8; i++)
        #pragma unroll
        for (int j = 0; j < 8; j++) acc[i][j] = 0.0f;

    for (int kk = 0; kk < 128; kk += BK) {
        float4 a4 = avalid ? *(const float4*)(arow + kk + lk4) : make_float4(0.f, 0.f, 0.f, 0.f);
        float4 b4 = *(const float4*)(wrow + kk + lk4);

        __syncthreads();
        sA[(lk4 + 0) * SLD + lr] = a4.x;
        sA[(lk4 + 1) * SLD + lr] = a4.y;
        sA[(lk4 + 2) * SLD + lr] = a4.z;
        sA[(lk4 + 3) * SLD + lr] = a4.w;
        sB[(lk4 + 0) * SLD + lr] = b4.x;
        sB[(lk4 + 1) * SLD + lr] = b4.y;
        sB[(lk4 + 2) * SLD + lr] = b4.z;
        sB[(lk4 + 3) * SLD + lr] = b4.w;
        __syncthreads();

        #pragma unroll
        for (int k = 0; k < BK; k++) {
            float4 a0 = *(const float4*)&sA[k * SLD + row0];
            float4 a1 = *(const float4*)&sA[k * SLD + row0 + 4];
            float4 b0 = *(const float4*)&sB[k * SLD + col0];
            float4 b1 = *(const float4*)&sB[k * SLD + col0 + 4];
            float af[8] = {a0.x, a0.y, a0.z, a0.w, a1.x, a1.y, a1.z, a1.w};
            float bf[8] = {b0.x, b0.y, b0.z, b0.w, b1.x, b1.y, b1.z, b1.w};
            #pragma unroll
            for (int i = 0; i < 8; i++)
                #pragma unroll
                for (int j = 0; j < 8; j++)
                    acc[i][j] += af[i] * bf[j];
        }
    }

    const int jg0 = jBase + col0;
    float* obase; int jl;
    if (jg0 < n0) { obase = out0; jl = jg0;      }
    else          { obase = out1; jl = jg0 - n0; }

    #pragma unroll
    for (int i = 0; i < 8; i++) {
        int row = rowBase + row0 + i;
        if (row < N) {
            float4 v0 = make_float4(acc[i][0], acc[i][1], acc[i][2], acc[i][3]);
            float4 v1 = make_float4(acc[i][4], acc[i][5], acc[i][6], acc[i][7]);
            *(float4*)(obase + (size_t)row * LD + jl)     = v0;
            *(float4*)(obase + (size_t)row * LD + jl + 4) = v1;
        }
    }
}

// ---------------------------------------------------------------------------
// Scatter-add of D-dim messages along edges: agg[dst] += g_t1[src].
// One thread per (edge, float4-chunk); decoded int32 index loads broadcast
// within the warp.
// ---------------------------------------------------------------------------
template <int LAYER>   // 1: D=128 -> g_agg1 ; 2: D=64 -> g_agg2
__global__ void scatter_kernel(int E)
{
    constexpr int D    = (LAYER == 1) ? 128 : 64;
    constexpr int CH   = D / 4;
    constexpr int CLOG = (LAYER == 1) ? 5 : 4;
    float* agg = (LAYER == 1) ? g_agg1 : g_agg2;

    long long gid = (long long)blockIdx.x * blockDim.x + threadIdx.x;
    int e = (int)(gid >> CLOG);
    int c = (int)(gid & (CH - 1));
    if (e >= E) return;
    int src = g_src[e];
    int dst = g_dst[e];
    float4 m = *(const float4*)(g_t1 + (size_t)src * D + c * 4);
    red_add_v4(agg + (size_t)dst * D + c * 4, m);
}

// ---------------------------------------------------------------------------
// finalize1: h = relu(pre + agg1/max(deg,1) + b1)   (in-place into g_pre)
// ---------------------------------------------------------------------------
__global__ void finalize1_kernel(const float* __restrict__ b1, int N) {
    int gid  = blockIdx.x * blockDim.x + threadIdx.x;
    int node = gid >> 5;
    int c    = gid & 31;
    if (node >= N) return;
    float inv = 1.0f / fmaxf(g_deg[node], 1.0f);
    size_t off = (size_t)node * 128 + c * 4;
    float4 pre = *(const float4*)&g_pre [off];
    float4 ag  = *(const float4*)&g_agg1[off];
    float4 b   = *(const float4*)&b1[c * 4];
    float4 h;
    h.x = fmaxf(pre.x + ag.x * inv + b.x, 0.0f);
    h.y = fmaxf(pre.y + ag.y * inv + b.y, 0.0f);
    h.z = fmaxf(pre.z + ag.z * inv + b.z, 0.0f);
    h.w = fmaxf(pre.w + ag.w * inv + b.w, 0.0f);
    *(float4*)&g_pre[off] = h;
}

// ---------------------------------------------------------------------------
// finalize2: out += agg2/max(deg,1) + b2      (out already holds h @ W_r2^T)
// ---------------------------------------------------------------------------
__global__ void finalize2_kernel(const float* __restrict__ b2,
                                 float* __restrict__ out, int N) {
    int gid  = blockIdx.x * blockDim.x + threadIdx.x;
    int node = gid >> 4;
    int c    = gid & 15;
    if (node >= N) return;
    float inv = 1.0f / fmaxf(g_deg[node], 1.0f);
    size_t off = (size_t)node * 64 + c * 4;
    float4 r  = *(const float4*)&out   [off];
    float4 ag = *(const float4*)&g_agg2[off];
    float4 b  = *(const float4*)&b2[c * 4];
    r.x += ag.x * inv + b.x;
    r.y += ag.y * inv + b.y;
    r.z += ag.z * inv + b.z;
    r.w += ag.w * inv + b.w;
    *(float4*)&out[off] = r;
}

// ---------------------------------------------------------------------------
// Launch — kernel launches ONLY (graph-capture-safe).
// ---------------------------------------------------------------------------
extern "C" void kernel_launch(void* const* d_in, const int* in_sizes, int n_in,
                              void* d_out, int out_size)
{
    const float* x   = (const float*)d_in[0];
    const void*  ei  = d_in[1];
    const float* Wl1 = (const float*)d_in[2];
    const float* b1  = (const float*)d_in[3];
    const float* Wr1 = (const float*)d_in[4];
    const float* Wl2 = (const float*)d_in[5];
    const float* b2  = (const float*)d_in[6];
    const float* Wr2 = (const float*)d_in[7];
    float*       out = (float*)d_out;

    const int N = in_sizes[0] / 128;
    const int E = in_sizes[1] / 2;

    // 0) zero scratch, sniff index dtype, decode indices + degree
    {
        int tot = N * 193;
        zero_scratch<<<(tot + 255) / 256, 256>>>(N);
        detect_kernel<<<1, 32>>>((const int*)ei);
        decode_deg_kernel<<<(E + 255) / 256, 256>>>(ei, E);
    }

    // 1) layer-1 transforms: g_t1 = x @ W_l1^T ; g_pre = x @ W_r1^T
    {
        dim3 grid((N + 127) / 128, 2);
        gemm_dual<1><<<grid, 256>>>(x, Wl1, Wr1, nullptr, N);
    }

    // 2) aggregate g_t1 along edges into g_agg1
    {
        long long tot = (long long)E * 32;
        scatter_kernel<1><<<(int)((tot + 255) / 256), 256>>>(E);
    }

    // 3) h = relu(pre + agg1/deg + b1)  (in-place in g_pre)
    finalize1_kernel<<<(N * 32 + 255) / 256, 256>>>(b1, N);

    // 4) layer-2 transforms: g_t1 = h @ W_l2^T (ld 64) ; out = h @ W_r2^T
    {
        dim3 grid((N + 127) / 128, 1);
        gemm_dual<2><<<grid, 256>>>(nullptr, Wl2, Wr2, out, N);
    }

    // 5) aggregate g_t1 along edges into g_agg2
    {
        long long tot = (long long)E * 16;
        scatter_kernel<2><<<(int)((tot + 255) / 256), 256>>>(E);
    }

    // 6) out += agg2/deg + b2
    finalize2_kernel<<<(N * 16 + 255) / 256, 256>>>(b2, out, N);
}

// round 5
// speedup vs baseline: 1.1803x; 1.1803x over previous
#include <cuda_runtime.h>
#include <cstdint>

// Problem-size upper bounds (fixed by the dataset).
#define NMAX 100000
#define EMAX 1600000

// ---------------------------------------------------------------------------
// Static device scratch (allocation-free per harness rules).
// ---------------------------------------------------------------------------
__device__ float g_t1 [NMAX * 128];  // layer1 msgs t1 = x@W_l1^T ; reused as layer2 u (ld 64)
__device__ float g_pre[NMAX * 128];  // layer1 pre = x@W_r1^T ; becomes h in-place
__device__ float g_agg1[NMAX * 128]; // layer1 aggregation
__device__ float g_agg2[NMAX * 64];  // layer2 aggregation
__device__ float g_deg [NMAX];       // in-degree (float)
__device__ int   g_src [EMAX];       // decoded edge sources
__device__ int   g_dst [EMAX];       // decoded edge destinations
__device__ int   g_is64;             // 1 if edge_index is int64, 0 if int32

// ---------------------------------------------------------------------------
// Vectorized global reduction-add (no return), sm_90+.
// ---------------------------------------------------------------------------
__device__ __forceinline__ void red_add_v4(float* p, float4 v) {
#if defined(__CUDA_ARCH__) && (__CUDA_ARCH__ >= 900)
    asm volatile("red.global.add.v4.f32 [%0], {%1,%2,%3,%4};"
                 :: "l"(p), "f"(v.x), "f"(v.y), "f"(v.z), "f"(v.w) : "memory");
#else
    atomicAdd(p + 0, v.x);
    atomicAdd(p + 1, v.y);
    atomicAdd(p + 2, v.z);
    atomicAdd(p + 3, v.w);
#endif
}

// ---------------------------------------------------------------------------
// tf32 helpers
// ---------------------------------------------------------------------------
__device__ __forceinline__ uint32_t f2tf(float x) {
    uint32_t r;
    asm("cvt.rna.tf32.f32 %0, %1;" : "=r"(r) : "f"(x));
    return r;
}

__device__ __forceinline__ void mma_tf32(float c[4], const uint32_t a[4],
                                         uint32_t b0, uint32_t b1) {
    asm volatile(
        "mma.sync.aligned.m16n8k8.row.col.f32.tf32.tf32.f32 "
        "{%0,%1,%2,%3}, {%4,%5,%6,%7}, {%8,%9}, {%0,%1,%2,%3};"
        : "+f"(c[0]), "+f"(c[1]), "+f"(c[2]), "+f"(c[3])
        : "r"(a[0]), "r"(a[1]), "r"(a[2]), "r"(a[3]), "r"(b0), "r"(b1));
}

// ---------------------------------------------------------------------------
// Detect edge_index dtype (int64 little-endian has zero high words).
// ---------------------------------------------------------------------------
__global__ void detect_kernel(const int* __restrict__ ei32) {
    if (threadIdx.x == 0 && blockIdx.x == 0) {
        int nz = 0;
        #pragma unroll
        for (int i = 1; i < 128; i += 2) nz |= ei32[i];
        g_is64 = (nz == 0) ? 1 : 0;
    }
}

// ---------------------------------------------------------------------------
// Decode indices to int32 arrays + count degrees.
// ---------------------------------------------------------------------------
__global__ void decode_deg_kernel(const void* __restrict__ ei, int E) {
    int e = blockIdx.x * blockDim.x + threadIdx.x;
    if (e >= E) return;
    int src, dst;
    if (g_is64) {
        const long long* p = (const long long*)ei;
        src = (int)p[e];
        dst = (int)p[E + e];
    } else {
        const int* p = (const int*)ei;
        src = p[e];
        dst = p[E + e];
    }
    g_src[e] = src;
    g_dst[e] = dst;
    atomicAdd(&g_deg[dst], 1.0f);
}

// ---------------------------------------------------------------------------
// Zero scratch: agg1 (N*128) + agg2 (N*64) + deg (N)
// ---------------------------------------------------------------------------
__global__ void zero_scratch(int N) {
    int i = blockIdx.x * blockDim.x + threadIdx.x;
    int n128 = N * 128;
    int n192 = N * 192;
    int tot  = N * 193;
    if (i >= tot) return;
    if (i < n128)       g_agg1[i] = 0.0f;
    else if (i < n192)  g_agg2[i - n128] = 0.0f;
    else                g_deg [i - n192] = 0.0f;
}

// ---------------------------------------------------------------------------
// Tensor-core dual-output GEMM: C = A[N,128] @ Wcat^T, K = 128.
// Weights split into tf32 hi+lo (removes B-side truncation error entirely):
//   C = A_tf32 @ (W_hi + W_lo)^T   — only A truncation remains (~3e-4 RMS).
// LAYER==1: Wcat = [W_l1;W_r1] (256 cols, grid.y=2), out0=g_t1, out1=g_pre (ld128)
// LAYER==2: Wcat = [W_l2;W_r2] (128 cols, grid.y=1), out0=g_t1, out1=d_out (ld64)
// BM=128, BN=128, BK=16. 8 warps; warp tile 64x32 = 4x4 m16n8k8 mma tiles.
// ---------------------------------------------------------------------------
template <int LAYER>
__global__ __launch_bounds__(256) void gemm_tc(
    const float* __restrict__ Aext,
    const float* __restrict__ W0,
    const float* __restrict__ W1,
    float* __restrict__ outExt,
    int N)
{
    constexpr int n0 = (LAYER == 1) ? 128 : 64;
    constexpr int LD = (LAYER == 1) ? 128 : 64;
    const float* A    = (LAYER == 1) ? Aext : g_pre;
    float*       out0 = g_t1;
    float*       out1 = (LAYER == 1) ? g_pre : outExt;

    constexpr int SL = 20;  // smem row stride (floats): bank = 4r+c → conflict-free frags
    __shared__ uint32_t sA [128 * SL];
    __shared__ uint32_t sBh[128 * SL];
    __shared__ uint32_t sBl[128 * SL];

    const int tid  = threadIdx.x;
    const int lane = tid & 31;
    const int wid  = tid >> 5;
    const int wm   = wid >> 2;          // 0..1 : warp row  (64 rows)
    const int wn   = wid & 3;           // 0..3 : warp col  (32 cols)
    const int gq   = lane >> 2;         // 0..7
    const int q    = lane & 3;          // 0..3

    const int rowBase = blockIdx.x * 128;
    const int jBase   = blockIdx.y * 128;

    // staging mapping: 2 threads per row, 8 floats each
    const int sr = tid >> 1;            // 0..127
    const int cb = (tid & 1) * 8;       // 0 or 8

    const int  gr     = rowBase + sr;
    const bool avalid = gr < N;
    const float* arow = A + (size_t)gr * 128;
    const float* wrow;
    {
        int jr = jBase + sr;
        wrow = (jr < n0) ? (W0 + (size_t)jr * 128) : (W1 + (size_t)(jr - n0) * 128);
    }

    float c[4][4][4];
    #pragma unroll
    for (int tm = 0; tm < 4; tm++)
        #pragma unroll
        for (int tn = 0; tn < 4; tn++)
            #pragma unroll
            for (int i = 0; i < 4; i++) c[tm][tn][i] = 0.0f;

    #pragma unroll 1
    for (int kt = 0; kt < 8; kt++) {
        const int k0 = kt * 16;
        float4 a0v = avalid ? *(const float4*)(arow + k0 + cb)
                            : make_float4(0.f, 0.f, 0.f, 0.f);
        float4 a1v = avalid ? *(const float4*)(arow + k0 + cb + 4)
                            : make_float4(0.f, 0.f, 0.f, 0.f);
        float4 w0v = *(const float4*)(wrow + k0 + cb);
        float4 w1v = *(const float4*)(wrow + k0 + cb + 4);

        __syncthreads();   // previous iteration's compute done
        {
            uint32_t* pa = sA + sr * SL + cb;
            pa[0] = f2tf(a0v.x); pa[1] = f2tf(a0v.y);
            pa[2] = f2tf(a0v.z); pa[3] = f2tf(a0v.w);
            pa[4] = f2tf(a1v.x); pa[5] = f2tf(a1v.y);
            pa[6] = f2tf(a1v.z); pa[7] = f2tf(a1v.w);

            float wf[8] = {w0v.x, w0v.y, w0v.z, w0v.w, w1v.x, w1v.y, w1v.z, w1v.w};
            uint32_t* ph = sBh + sr * SL + cb;
            uint32_t* pl = sBl + sr * SL + cb;
            #pragma unroll
            for (int j = 0; j < 8; j++) {
                uint32_t hi = f2tf(wf[j]);
                ph[j] = hi;
                pl[j] = f2tf(wf[j] - __uint_as_float(hi));
            }
        }
        __syncthreads();

        #pragma unroll
        for (int k8 = 0; k8 < 16; k8 += 8) {
            uint32_t af[4][4];
            #pragma unroll
            for (int tm = 0; tm < 4; tm++) {
                int r = (wm * 64 + tm * 16 + gq) * SL + k8 + q;
                af[tm][0] = sA[r];
                af[tm][1] = sA[r + 8 * SL];
                af[tm][2] = sA[r + 4];
                af[tm][3] = sA[r + 8 * SL + 4];
            }
            #pragma unroll
            for (int tn = 0; tn < 4; tn++) {
                int b = (wn * 32 + tn * 8 + gq) * SL + k8 + q;
                uint32_t bh0 = sBh[b], bh1 = sBh[b + 4];
                uint32_t bl0 = sBl[b], bl1 = sBl[b + 4];
                #pragma unroll
                for (int tm = 0; tm < 4; tm++) {
                    mma_tf32(c[tm][tn], af[tm], bh0, bh1);
                    mma_tf32(c[tm][tn], af[tm], bl0, bl1);
                }
            }
        }
    }

    // epilogue: each thread owns (row, row+8) x (col, col+1) per (tm,tn) tile
    #pragma unroll
    for (int tn = 0; tn < 4; tn++) {
        int col = jBase + wn * 32 + tn * 8 + q * 2;
        float* obase; int jl;
        if (col < n0) { obase = out0; jl = col;      }
        else          { obase = out1; jl = col - n0; }
        #pragma unroll
        for (int tm = 0; tm < 4; tm++) {
            int row0 = rowBase + wm * 64 + tm * 16 + gq;
            int row1 = row0 + 8;
            if (row0 < N) {
                float2 v = make_float2(c[tm][tn][0], c[tm][tn][1]);
                *(float2*)(obase + (size_t)row0 * LD + jl) = v;
            }
            if (row1 < N) {
                float2 v = make_float2(c[tm][tn][2], c[tm][tn][3]);
                *(float2*)(obase + (size_t)row1 * LD + jl) = v;
            }
        }
    }
}

// ---------------------------------------------------------------------------
// Scatter-add of D-dim messages along edges: agg[dst] += g_t1[src].
// ---------------------------------------------------------------------------
template <int LAYER>   // 1: D=128 -> g_agg1 ; 2: D=64 -> g_agg2
__global__ void scatter_kernel(int E)
{
    constexpr int D    = (LAYER == 1) ? 128 : 64;
    constexpr int CH   = D / 4;
    constexpr int CLOG = (LAYER == 1) ? 5 : 4;
    float* agg = (LAYER == 1) ? g_agg1 : g_agg2;

    long long gid = (long long)blockIdx.x * blockDim.x + threadIdx.x;
    int e = (int)(gid >> CLOG);
    int c = (int)(gid & (CH - 1));
    if (e >= E) return;
    int src = g_src[e];
    int dst = g_dst[e];
    float4 m = *(const float4*)(g_t1 + (size_t)src * D + c * 4);
    red_add_v4(agg + (size_t)dst * D + c * 4, m);
}

// ---------------------------------------------------------------------------
// finalize1: h = relu(pre + agg1/max(deg,1) + b1)   (in-place into g_pre)
// ---------------------------------------------------------------------------
__global__ void finalize1_kernel(const float* __restrict__ b1, int N) {
    int gid  = blockIdx.x * blockDim.x + threadIdx.x;
    int node = gid >> 5;
    int c    = gid & 31;
    if (node >= N) return;
    float inv = 1.0f / fmaxf(g_deg[node], 1.0f);
    size_t off = (size_t)node * 128 + c * 4;
    float4 pre = *(const float4*)&g_pre [off];
    float4 ag  = *(const float4*)&g_agg1[off];
    float4 b   = *(const float4*)&b1[c * 4];
    float4 h;
    h.x = fmaxf(pre.x + ag.x * inv + b.x, 0.0f);
    h.y = fmaxf(pre.y + ag.y * inv + b.y, 0.0f);
    h.z = fmaxf(pre.z + ag.z * inv + b.z, 0.0f);
    h.w = fmaxf(pre.w + ag.w * inv + b.w, 0.0f);
    *(float4*)&g_pre[off] = h;
}

// ---------------------------------------------------------------------------
// finalize2: out += agg2/max(deg,1) + b2      (out already holds h @ W_r2^T)
// ---------------------------------------------------------------------------
__global__ void finalize2_kernel(const float* __restrict__ b2,
                                 float* __restrict__ out, int N) {
    int gid  = blockIdx.x * blockDim.x + threadIdx.x;
    int node = gid >> 4;
    int c    = gid & 15;
    if (node >= N) return;
    float inv = 1.0f / fmaxf(g_deg[node], 1.0f);
    size_t off = (size_t)node * 64 + c * 4;
    float4 r  = *(const float4*)&out   [off];
    float4 ag = *(const float4*)&g_agg2[off];
    float4 b  = *(const float4*)&b2[c * 4];
    r.x += ag.x * inv + b.x;
    r.y += ag.y * inv + b.y;
    r.z += ag.z * inv + b.z;
    r.w += ag.w * inv + b.w;
    *(float4*)&out[off] = r;
}

// ---------------------------------------------------------------------------
// Launch — kernel launches ONLY (graph-capture-safe).
// ---------------------------------------------------------------------------
extern "C" void kernel_launch(void* const* d_in, const int* in_sizes, int n_in,
                              void* d_out, int out_size)
{
    const float* x   = (const float*)d_in[0];
    const void*  ei  = d_in[1];
    const float* Wl1 = (const float*)d_in[2];
    const float* b1  = (const float*)d_in[3];
    const float* Wr1 = (const float*)d_in[4];
    const float* Wl2 = (const float*)d_in[5];
    const float* b2  = (const float*)d_in[6];
    const float* Wr2 = (const float*)d_in[7];
    float*       out = (float*)d_out;

    const int N = in_sizes[0] / 128;
    const int E = in_sizes[1] / 2;

    // 0) zero scratch, sniff index dtype, decode indices + degree
    {
        int tot = N * 193;
        zero_scratch<<<(tot + 255) / 256, 256>>>(N);
        detect_kernel<<<1, 32>>>((const int*)ei);
        decode_deg_kernel<<<(E + 255) / 256, 256>>>(ei, E);
    }

    // 1) layer-1 transforms (tensor cores): g_t1 = x@W_l1^T ; g_pre = x@W_r1^T
    {
        dim3 grid((N + 127) / 128, 2);
        gemm_tc<1><<<grid, 256>>>(x, Wl1, Wr1, nullptr, N);
    }

    // 2) aggregate g_t1 along edges into g_agg1
    {
        long long tot = (long long)E * 32;
        scatter_kernel<1><<<(int)((tot + 255) / 256), 256>>>(E);
    }

    // 3) h = relu(pre + agg1/deg + b1)  (in-place in g_pre)
    finalize1_kernel<<<(N * 32 + 255) / 256, 256>>>(b1, N);

    // 4) layer-2 transforms: g_t1 = h@W_l2^T (ld 64) ; out = h@W_r2^T
    {
        dim3 grid((N + 127) / 128, 1);
        gemm_tc<2><<<grid, 256>>>(nullptr, Wl2, Wr2, out, N);
    }

    // 5) aggregate g_t1 along edges into g_agg2
    {
        long long tot = (long long)E * 16;
        scatter_kernel<2><<<(int)((tot + 255) / 256), 256>>>(E);
    }

    // 6) out += agg2/deg + b2
    finalize2_kernel<<<(N * 16 + 255) / 256, 256>>>(b2, out, N);
}

// round 6
// speedup vs baseline: 2.0482x; 1.7354x over previous
#include <cuda_runtime.h>
#include <cstdint>

// Problem-size upper bounds (fixed by the dataset).
#define NMAX 100000
#define EMAX 1600000
#define NB_MAX ((NMAX + 1023) / 1024)   // 98 scan blocks

// ---------------------------------------------------------------------------
// Static device scratch (allocation-free per harness rules).
// ---------------------------------------------------------------------------
__device__ float g_t1 [NMAX * 128];  // layer1 msgs t1 = x@W_l1^T ; reused as layer2 u (ld 64)
__device__ float g_pre[NMAX * 128];  // layer1 pre = x@W_r1^T ; becomes h in-place
__device__ int   g_src [EMAX];       // decoded edge sources
__device__ int   g_dst [EMAX];       // decoded edge destinations
__device__ int   g_cnt [NMAX];       // in-degree counters
__device__ int   g_rowptr[NMAX + 1]; // CSR row pointers (by dst)
__device__ int   g_fill[NMAX];       // fill cursors for reorder
__device__ int   g_eidx[EMAX];       // CSR: src indices sorted by dst
__device__ int   g_bsum[NB_MAX];     // scan block sums
__device__ int   g_boff[NB_MAX];     // scan block offsets
__device__ int   g_is64;             // 1 if edge_index is int64, 0 if int32

// ---------------------------------------------------------------------------
// tf32 helpers
// ---------------------------------------------------------------------------
__device__ __forceinline__ uint32_t f2tf(float x) {
    uint32_t r;
    asm("cvt.rna.tf32.f32 %0, %1;" : "=r"(r) : "f"(x));
    return r;
}

__device__ __forceinline__ void mma_tf32(float c[4], const uint32_t a[4],
                                         uint32_t b0, uint32_t b1) {
    asm volatile(
        "mma.sync.aligned.m16n8k8.row.col.f32.tf32.tf32.f32 "
        "{%0,%1,%2,%3}, {%4,%5,%6,%7}, {%8,%9}, {%0,%1,%2,%3};"
        : "+f"(c[0]), "+f"(c[1]), "+f"(c[2]), "+f"(c[3])
        : "r"(a[0]), "r"(a[1]), "r"(a[2]), "r"(a[3]), "r"(b0), "r"(b1));
}

// ---------------------------------------------------------------------------
// Detect edge_index dtype (int64 little-endian has zero high words).
// ---------------------------------------------------------------------------
__global__ void detect_kernel(const int* __restrict__ ei32) {
    if (threadIdx.x == 0 && blockIdx.x == 0) {
        int nz = 0;
        #pragma unroll
        for (int i = 1; i < 128; i += 2) nz |= ei32[i];
        g_is64 = (nz == 0) ? 1 : 0;
    }
}

__global__ void zero_cnt(int N) {
    int i = blockIdx.x * blockDim.x + threadIdx.x;
    if (i < N) g_cnt[i] = 0;
}

// ---------------------------------------------------------------------------
// Decode indices + count in-degrees.
// ---------------------------------------------------------------------------
__global__ void decode_kernel(const void* __restrict__ ei, int E) {
    int e = blockIdx.x * blockDim.x + threadIdx.x;
    if (e >= E) return;
    int src, dst;
    if (g_is64) {
        const long long* p = (const long long*)ei;
        src = (int)p[e];
        dst = (int)p[E + e];
    } else {
        const int* p = (const int*)ei;
        src = p[e];
        dst = p[E + e];
    }
    g_src[e] = src;
    g_dst[e] = dst;
    atomicAdd(&g_cnt[dst], 1);
}

// ---------------------------------------------------------------------------
// 3-kernel exclusive prefix scan of g_cnt -> g_rowptr  (N <= 1024*1024)
// ---------------------------------------------------------------------------
__global__ void scan_block(int N) {
    __shared__ int sh[1024];
    int t = threadIdx.x;
    int i = blockIdx.x * 1024 + t;
    int v = (i < N) ? g_cnt[i] : 0;
    sh[t] = v;
    __syncthreads();
    #pragma unroll
    for (int off = 1; off < 1024; off <<= 1) {
        int x = (t >= off) ? sh[t - off] : 0;
        __syncthreads();
        sh[t] += x;
        __syncthreads();
    }
    if (i < N) g_rowptr[i] = sh[t] - v;          // block-local exclusive
    if (t == 1023) g_bsum[blockIdx.x] = sh[1023];
}

__global__ void scan_partials(int nb) {
    __shared__ int sh[1024];
    int t = threadIdx.x;
    int v = (t < nb) ? g_bsum[t] : 0;
    sh[t] = v;
    __syncthreads();
    #pragma unroll
    for (int off = 1; off < 1024; off <<= 1) {
        int x = (t >= off) ? sh[t - off] : 0;
        __syncthreads();
        sh[t] += x;
        __syncthreads();
    }
    if (t < nb) g_boff[t] = sh[t] - v;           // exclusive
}

__global__ void scan_add(int N, int E) {
    int i = blockIdx.x * blockDim.x + threadIdx.x;
    if (i < N) {
        int val = g_rowptr[i] + g_boff[i >> 10];
        g_rowptr[i] = val;
        g_fill[i]   = val;
    }
    if (i == 0) g_rowptr[N] = E;
}

// ---------------------------------------------------------------------------
// Reorder: place src indices into dst-sorted CSR order.
// ---------------------------------------------------------------------------
__global__ void reorder_kernel(int E) {
    int e = blockIdx.x * blockDim.x + threadIdx.x;
    if (e >= E) return;
    int dst = g_dst[e];
    int pos = atomicAdd(&g_fill[dst], 1);
    g_eidx[pos] = g_src[e];
}

// ---------------------------------------------------------------------------
// Tensor-core dual-output GEMM: C = A[N,128] @ Wcat^T, K = 128.
// Weights split into tf32 hi+lo; only A truncation remains (~3e-4 RMS).
// LAYER==1: Wcat = [W_l1;W_r1] (grid.y=2), out0=g_t1 (ld128), out1=g_pre (ld128)
// LAYER==2: Wcat = [W_l2;W_r2] (grid.y=1), out0=g_t1 (ld64),  out1=d_out (ld64)
// ---------------------------------------------------------------------------
template <int LAYER>
__global__ __launch_bounds__(256) void gemm_tc(
    const float* __restrict__ Aext,
    const float* __restrict__ W0,
    const float* __restrict__ W1,
    float* __restrict__ outExt,
    int N)
{
    constexpr int n0 = (LAYER == 1) ? 128 : 64;
    constexpr int LD = (LAYER == 1) ? 128 : 64;
    const float* A    = (LAYER == 1) ? Aext : g_pre;
    float*       out0 = g_t1;
    float*       out1 = (LAYER == 1) ? g_pre : outExt;

    constexpr int SL = 20;
    __shared__ uint32_t sA [128 * SL];
    __shared__ uint32_t sBh[128 * SL];
    __shared__ uint32_t sBl[128 * SL];

    const int tid  = threadIdx.x;
    const int lane = tid & 31;
    const int wid  = tid >> 5;
    const int wm   = wid >> 2;
    const int wn   = wid & 3;
    const int gq   = lane >> 2;
    const int q    = lane & 3;

    const int rowBase = blockIdx.x * 128;
    const int jBase   = blockIdx.y * 128;

    const int sr = tid >> 1;
    const int cb = (tid & 1) * 8;

    const int  gr     = rowBase + sr;
    const bool avalid = gr < N;
    const float* arow = A + (size_t)gr * 128;
    const float* wrow;
    {
        int jr = jBase + sr;
        wrow = (jr < n0) ? (W0 + (size_t)jr * 128) : (W1 + (size_t)(jr - n0) * 128);
    }

    float c[4][4][4];
    #pragma unroll
    for (int tm = 0; tm < 4; tm++)
        #pragma unroll
        for (int tn = 0; tn < 4; tn++)
            #pragma unroll
            for (int i = 0; i < 4; i++) c[tm][tn][i] = 0.0f;

    #pragma unroll 1
    for (int kt = 0; kt < 8; kt++) {
        const int k0 = kt * 16;
        float4 a0v = avalid ? *(const float4*)(arow + k0 + cb)
                            : make_float4(0.f, 0.f, 0.f, 0.f);
        float4 a1v = avalid ? *(const float4*)(arow + k0 + cb + 4)
                            : make_float4(0.f, 0.f, 0.f, 0.f);
        float4 w0v = *(const float4*)(wrow + k0 + cb);
        float4 w1v = *(const float4*)(wrow + k0 + cb + 4);

        __syncthreads();
        {
            uint32_t* pa = sA + sr * SL + cb;
            pa[0] = f2tf(a0v.x); pa[1] = f2tf(a0v.y);
            pa[2] = f2tf(a0v.z); pa[3] = f2tf(a0v.w);
            pa[4] = f2tf(a1v.x); pa[5] = f2tf(a1v.y);
            pa[6] = f2tf(a1v.z); pa[7] = f2tf(a1v.w);

            float wf[8] = {w0v.x, w0v.y, w0v.z, w0v.w, w1v.x, w1v.y, w1v.z, w1v.w};
            uint32_t* ph = sBh + sr * SL + cb;
            uint32_t* pl = sBl + sr * SL + cb;
            #pragma unroll
            for (int j = 0; j < 8; j++) {
                uint32_t hi = f2tf(wf[j]);
                ph[j] = hi;
                pl[j] = f2tf(wf[j] - __uint_as_float(hi));
            }
        }
        __syncthreads();

        #pragma unroll
        for (int k8 = 0; k8 < 16; k8 += 8) {
            uint32_t af[4][4];
            #pragma unroll
            for (int tm = 0; tm < 4; tm++) {
                int r = (wm * 64 + tm * 16 + gq) * SL + k8 + q;
                af[tm][0] = sA[r];
                af[tm][1] = sA[r + 8 * SL];
                af[tm][2] = sA[r + 4];
                af[tm][3] = sA[r + 8 * SL + 4];
            }
            #pragma unroll
            for (int tn = 0; tn < 4; tn++) {
                int b = (wn * 32 + tn * 8 + gq) * SL + k8 + q;
                uint32_t bh0 = sBh[b], bh1 = sBh[b + 4];
                uint32_t bl0 = sBl[b], bl1 = sBl[b + 4];
                #pragma unroll
                for (int tm = 0; tm < 4; tm++) {
                    mma_tf32(c[tm][tn], af[tm], bh0, bh1);
                    mma_tf32(c[tm][tn], af[tm], bl0, bl1);
                }
            }
        }
    }

    #pragma unroll
    for (int tn = 0; tn < 4; tn++) {
        int col = jBase + wn * 32 + tn * 8 + q * 2;
        float* obase; int jl;
        if (col < n0) { obase = out0; jl = col;      }
        else          { obase = out1; jl = col - n0; }
        #pragma unroll
        for (int tm = 0; tm < 4; tm++) {
            int row0 = rowBase + wm * 64 + tm * 16 + gq;
            int row1 = row0 + 8;
            if (row0 < N) {
                float2 v = make_float2(c[tm][tn][0], c[tm][tn][1]);
                *(float2*)(obase + (size_t)row0 * LD + jl) = v;
            }
            if (row1 < N) {
                float2 v = make_float2(c[tm][tn][2], c[tm][tn][3]);
                *(float2*)(obase + (size_t)row1 * LD + jl) = v;
            }
        }
    }
}

// ---------------------------------------------------------------------------
// CSR gather + fused finalize. One warp per node.
// LAYER==1 (D=128): lane accumulates float4 at offset lane*4 over in-edges of
//   node; then h = relu(pre + mean + b1) written in-place to g_pre.
// LAYER==2 (D=64): lane accumulates float2 at offset lane*2;
//   out[node] += mean + b2 (out already holds h @ W_r2^T).
// ---------------------------------------------------------------------------
template <int LAYER>
__global__ __launch_bounds__(256) void gather_finalize(
    const float* __restrict__ bias,
    float* __restrict__ outExt,
    int N)
{
    int gw   = (blockIdx.x * blockDim.x + threadIdx.x) >> 5;
    int lane = threadIdx.x & 31;
    if (gw >= N) return;

    int start = g_rowptr[gw];
    int end   = g_rowptr[gw + 1];
    float inv = 1.0f / (float)max(end - start, 1);

    if (LAYER == 1) {
        const float* msg = g_t1;
        float4 acc = make_float4(0.f, 0.f, 0.f, 0.f);
        int i = start;
        for (; i + 1 < end; i += 2) {
            int s0 = g_eidx[i];
            int s1 = g_eidx[i + 1];
            float4 v0 = *(const float4*)(msg + (size_t)s0 * 128 + lane * 4);
            float4 v1 = *(const float4*)(msg + (size_t)s1 * 128 + lane * 4);
            acc.x += v0.x; acc.y += v0.y; acc.z += v0.z; acc.w += v0.w;
            acc.x += v1.x; acc.y += v1.y; acc.z += v1.z; acc.w += v1.w;
        }
        if (i < end) {
            int s0 = g_eidx[i];
            float4 v0 = *(const float4*)(msg + (size_t)s0 * 128 + lane * 4);
            acc.x += v0.x; acc.y += v0.y; acc.z += v0.z; acc.w += v0.w;
        }
        size_t off = (size_t)gw * 128 + lane * 4;
        float4 pre = *(const float4*)&g_pre[off];
        float4 b   = *(const float4*)&bias[lane * 4];
        float4 h;
        h.x = fmaxf(pre.x + acc.x * inv + b.x, 0.0f);
        h.y = fmaxf(pre.y + acc.y * inv + b.y, 0.0f);
        h.z = fmaxf(pre.z + acc.z * inv + b.z, 0.0f);
        h.w = fmaxf(pre.w + acc.w * inv + b.w, 0.0f);
        *(float4*)&g_pre[off] = h;
    } else {
        const float* msg = g_t1;   // holds layer2 messages (ld 64)
        float2 acc = make_float2(0.f, 0.f);
        int i = start;
        for (; i + 1 < end; i += 2) {
            int s0 = g_eidx[i];
            int s1 = g_eidx[i + 1];
            float2 v0 = *(const float2*)(msg + (size_t)s0 * 64 + lane * 2);
            float2 v1 = *(const float2*)(msg + (size_t)s1 * 64 + lane * 2);
            acc.x += v0.x; acc.y += v0.y;
            acc.x += v1.x; acc.y += v1.y;
        }
        if (i < end) {
            int s0 = g_eidx[i];
            float2 v0 = *(const float2*)(msg + (size_t)s0 * 64 + lane * 2);
            acc.x += v0.x; acc.y += v0.y;
        }
        size_t off = (size_t)gw * 64 + lane * 2;
        float2 r = *(const float2*)&outExt[off];
        float2 b = *(const float2*)&bias[lane * 2];
        r.x += acc.x * inv + b.x;
        r.y += acc.y * inv + b.y;
        *(float2*)&outExt[off] = r;
    }
}

// ---------------------------------------------------------------------------
// Launch — kernel launches ONLY (graph-capture-safe).
// ---------------------------------------------------------------------------
extern "C" void kernel_launch(void* const* d_in, const int* in_sizes, int n_in,
                              void* d_out, int out_size)
{
    const float* x   = (const float*)d_in[0];
    const void*  ei  = d_in[1];
    const float* Wl1 = (const float*)d_in[2];
    const float* b1  = (const float*)d_in[3];
    const float* Wr1 = (const float*)d_in[4];
    const float* Wl2 = (const float*)d_in[5];
    const float* b2  = (const float*)d_in[6];
    const float* Wr2 = (const float*)d_in[7];
    float*       out = (float*)d_out;

    const int N  = in_sizes[0] / 128;
    const int E  = in_sizes[1] / 2;
    const int nb = (N + 1023) / 1024;

    // 0) CSR build: counts -> scan -> reorder
    zero_cnt<<<(N + 255) / 256, 256>>>(N);
    detect_kernel<<<1, 32>>>((const int*)ei);
    decode_kernel<<<(E + 255) / 256, 256>>>(ei, E);
    scan_block<<<nb, 1024>>>(N);
    scan_partials<<<1, 1024>>>(nb);
    scan_add<<<(N + 255) / 256, 256>>>(N, E);
    reorder_kernel<<<(E + 255) / 256, 256>>>(E);

    // 1) layer-1 transforms (tensor cores): g_t1 = x@W_l1^T ; g_pre = x@W_r1^T
    {
        dim3 grid((N + 127) / 128, 2);
        gemm_tc<1><<<grid, 256>>>(x, Wl1, Wr1, nullptr, N);
    }

    // 2) gather + fused finalize1: g_pre <- relu(pre + mean(t1[nbrs]) + b1)
    gather_finalize<1><<<(N * 32 + 255) / 256, 256>>>(b1, nullptr, N);

    // 3) layer-2 transforms: g_t1 = h@W_l2^T (ld 64) ; out = h@W_r2^T
    {
        dim3 grid((N + 127) / 128, 1);
        gemm_tc<2><<<grid, 256>>>(nullptr, Wl2, Wr2, out, N);
    }

    // 4) gather + fused finalize2: out += mean(u[nbrs]) + b2
    gather_finalize<2><<<(N * 32 + 255) / 256, 256>>>(b2, out, N);
}